// round 1
// baseline (speedup 1.0000x reference)
#include <cuda_runtime.h>
#include <math.h>

#define D_MODEL 1024
#define HEADS 16
#define DK 64
#define BATCH 2
#define SEQ 2048
#define M_ROWS (BATCH * SEQ)   // 4096

// ---------------- scratch (static device globals; no allocation) -------------
__device__ float g_q[(size_t)BATCH * HEADS * SEQ * DK];     // [bh][s][dk]
__device__ float g_k[(size_t)BATCH * HEADS * SEQ * DK];
__device__ float g_v[(size_t)BATCH * HEADS * SEQ * DK];
__device__ float g_attn[(size_t)M_ROWS * D_MODEL];          // [b*S+s][H*dk]

// ---------------------------------------------------------------------------
// GEMM: C[M=4096, N=1024] = A[4096,1024] * W[1024,1024] + bias[N]
// headsplit=1 -> write to [b,h,s,dk] layout; headsplit=0 -> plain row-major.
// 128x128 tile, BK=16, 256 threads, 8x8 per-thread microtile.
// ---------------------------------------------------------------------------
#define GBM 128
#define GBN 128
#define GBK 16

__global__ void __launch_bounds__(256) gemm_bias_kernel(
    const float* __restrict__ A, const float* __restrict__ W,
    const float* __restrict__ bias, float* __restrict__ C, int headsplit)
{
    __shared__ float As[GBK][GBM];   // transposed A tile
    __shared__ float Ws[GBK][GBN];

    const int tid = threadIdx.x;
    const int m0 = blockIdx.y * GBM;
    const int n0 = blockIdx.x * GBN;
    const int tm = (tid / 16) * 8;
    const int tn = (tid % 16) * 8;

    // loader mapping
    const int arow  = tid >> 2;          // 0..63
    const int acol4 = (tid & 3) * 4;     // 0,4,8,12
    const int wrow  = tid >> 5;          // 0..7
    const int wcol4 = (tid & 31) * 4;    // 0..124

    float acc[8][8];
#pragma unroll
    for (int i = 0; i < 8; i++)
#pragma unroll
        for (int j = 0; j < 8; j++) acc[i][j] = 0.f;

    for (int k0 = 0; k0 < D_MODEL; k0 += GBK) {
        float4 a0 = *(const float4*)&A[(size_t)(m0 + arow) * D_MODEL + k0 + acol4];
        float4 a1 = *(const float4*)&A[(size_t)(m0 + arow + 64) * D_MODEL + k0 + acol4];
        float4 w0 = *(const float4*)&W[(size_t)(k0 + wrow) * D_MODEL + n0 + wcol4];
        float4 w1 = *(const float4*)&W[(size_t)(k0 + wrow + 8) * D_MODEL + n0 + wcol4];

        As[acol4 + 0][arow] = a0.x; As[acol4 + 1][arow] = a0.y;
        As[acol4 + 2][arow] = a0.z; As[acol4 + 3][arow] = a0.w;
        As[acol4 + 0][arow + 64] = a1.x; As[acol4 + 1][arow + 64] = a1.y;
        As[acol4 + 2][arow + 64] = a1.z; As[acol4 + 3][arow + 64] = a1.w;
        *(float4*)&Ws[wrow][wcol4]     = w0;
        *(float4*)&Ws[wrow + 8][wcol4] = w1;
        __syncthreads();

#pragma unroll
        for (int kk = 0; kk < GBK; ++kk) {
            float a[8], b[8];
            *(float4*)&a[0] = *(const float4*)&As[kk][tm];
            *(float4*)&a[4] = *(const float4*)&As[kk][tm + 4];
            *(float4*)&b[0] = *(const float4*)&Ws[kk][tn];
            *(float4*)&b[4] = *(const float4*)&Ws[kk][tn + 4];
#pragma unroll
            for (int i = 0; i < 8; i++)
#pragma unroll
                for (int j = 0; j < 8; j++)
                    acc[i][j] = fmaf(a[i], b[j], acc[i][j]);
        }
        __syncthreads();
    }

    // epilogue
#pragma unroll
    for (int i = 0; i < 8; i++) {
        const int m = m0 + tm + i;
#pragma unroll
        for (int jg = 0; jg < 8; jg += 4) {
            const int n = n0 + tn + jg;
            float4 v;
            v.x = acc[i][jg + 0] + bias[n + 0];
            v.y = acc[i][jg + 1] + bias[n + 1];
            v.z = acc[i][jg + 2] + bias[n + 2];
            v.w = acc[i][jg + 3] + bias[n + 3];
            if (headsplit) {
                const int b = m >> 11;          // /SEQ
                const int s = m & (SEQ - 1);
                const int h = n >> 6;           // /DK
                const int d = n & (DK - 1);
                *(float4*)&C[(((size_t)(b * HEADS + h) * SEQ) + s) * DK + d] = v;
            } else {
                *(float4*)&C[(size_t)m * D_MODEL + n] = v;
            }
        }
    }
}

// ---------------------------------------------------------------------------
// Flash attention (causal), fp32. Per block: 64 queries x full K sweep.
// grid: x = q-tile (reversed so long blocks start first), y = b*H+h.
// 256 threads = 16x16; each thread: 4x4 score tile and 4x4 output tile.
// ---------------------------------------------------------------------------
__global__ void __launch_bounds__(256) flash_kernel(
    const float* __restrict__ Q, const float* __restrict__ K,
    const float* __restrict__ V, float* __restrict__ Out)
{
    extern __shared__ float sm[];
    float* Qt = sm;              // [64 d][64 q]
    float* Kt = sm + 4096;       // [64 d][64 k]
    float* Vs = sm + 8192;       // [64 k][64 d]
    float* Ps = sm + 12288;      // [64 q][68]  (padded rows)

    const int qt = gridDim.x - 1 - blockIdx.x;   // long blocks first
    const int bh = blockIdx.y;
    const float* Qp = Q + (size_t)bh * SEQ * DK + (size_t)qt * 64 * DK;
    const float* Kp = K + (size_t)bh * SEQ * DK;
    const float* Vp = V + (size_t)bh * SEQ * DK;

    const int tid = threadIdx.x;
    const int ty = tid >> 4, tx = tid & 15;
    const int qr = ty * 4;       // query sub-row
    const int dc = tx * 4;       // key col in S-gemm / d col in O-gemm

    float m_i[4], l_i[4], o[4][4];
#pragma unroll
    for (int i = 0; i < 4; i++) {
        m_i[i] = -3.0e38f; l_i[i] = 0.f;
#pragma unroll
        for (int j = 0; j < 4; j++) o[i][j] = 0.f;
    }

    // load Q tile transposed
#pragma unroll
    for (int it = 0; it < 4; ++it) {
        int idx = tid + it * 256;            // float4 index 0..1023
        int r = idx >> 4; int c = (idx & 15) << 2;
        float4 qv = *(const float4*)&Qp[r * DK + c];
        Qt[(c + 0) * 64 + r] = qv.x; Qt[(c + 1) * 64 + r] = qv.y;
        Qt[(c + 2) * 64 + r] = qv.z; Qt[(c + 3) * 64 + r] = qv.w;
    }

    const float scale = 0.125f;  // 1/sqrt(64)

    for (int kt = 0; kt <= qt; ++kt) {
        __syncthreads();   // protect Kt/Vs/Ps from previous iteration readers
#pragma unroll
        for (int it = 0; it < 4; ++it) {
            int idx = tid + it * 256;
            int r = idx >> 4; int c = (idx & 15) << 2;
            float4 kv = *(const float4*)&Kp[(size_t)(kt * 64 + r) * DK + c];
            Kt[(c + 0) * 64 + r] = kv.x; Kt[(c + 1) * 64 + r] = kv.y;
            Kt[(c + 2) * 64 + r] = kv.z; Kt[(c + 3) * 64 + r] = kv.w;
            float4 vv = *(const float4*)&Vp[(size_t)(kt * 64 + r) * DK + c];
            *(float4*)&Vs[r * 64 + c] = vv;
        }
        __syncthreads();

        // S = Q K^T  (outer product over d)
        float s[4][4];
#pragma unroll
        for (int i = 0; i < 4; i++)
#pragma unroll
            for (int j = 0; j < 4; j++) s[i][j] = 0.f;

#pragma unroll 16
        for (int d0 = 0; d0 < 64; ++d0) {
            float a[4], b[4];
            *(float4*)a = *(const float4*)&Qt[d0 * 64 + qr];
            *(float4*)b = *(const float4*)&Kt[d0 * 64 + dc];
#pragma unroll
            for (int i = 0; i < 4; i++)
#pragma unroll
                for (int j = 0; j < 4; j++)
                    s[i][j] = fmaf(a[i], b[j], s[i][j]);
        }

        // scale + causal mask (only the diagonal tile needs masking)
        if (kt == qt) {
#pragma unroll
            for (int i = 0; i < 4; i++)
#pragma unroll
                for (int j = 0; j < 4; j++)
                    s[i][j] = ((dc + j) <= (qr + i)) ? s[i][j] * scale : -1.0e30f;
        } else {
#pragma unroll
            for (int i = 0; i < 4; i++)
#pragma unroll
                for (int j = 0; j < 4; j++) s[i][j] *= scale;
        }

        // online softmax
        float mnew[4], corr[4];
#pragma unroll
        for (int i = 0; i < 4; i++) {
            float rm = fmaxf(fmaxf(s[i][0], s[i][1]), fmaxf(s[i][2], s[i][3]));
            rm = fmaxf(rm, __shfl_xor_sync(0xffffffffu, rm, 1));
            rm = fmaxf(rm, __shfl_xor_sync(0xffffffffu, rm, 2));
            rm = fmaxf(rm, __shfl_xor_sync(0xffffffffu, rm, 4));
            rm = fmaxf(rm, __shfl_xor_sync(0xffffffffu, rm, 8));
            mnew[i] = fmaxf(m_i[i], rm);
            corr[i] = __expf(m_i[i] - mnew[i]);
            m_i[i] = mnew[i];
        }
#pragma unroll
        for (int i = 0; i < 4; i++) {
            float sum = 0.f;
#pragma unroll
            for (int j = 0; j < 4; j++) {
                float p = __expf(s[i][j] - mnew[i]);
                s[i][j] = p;
                sum += p;
            }
            sum += __shfl_xor_sync(0xffffffffu, sum, 1);
            sum += __shfl_xor_sync(0xffffffffu, sum, 2);
            sum += __shfl_xor_sync(0xffffffffu, sum, 4);
            sum += __shfl_xor_sync(0xffffffffu, sum, 8);
            l_i[i] = l_i[i] * corr[i] + sum;
#pragma unroll
            for (int j = 0; j < 4; j++) o[i][j] *= corr[i];
            *(float4*)&Ps[(qr + i) * 68 + dc] =
                make_float4(s[i][0], s[i][1], s[i][2], s[i][3]);
        }
        __syncthreads();

        // O += P V  (contraction over key index j0)
#pragma unroll 8
        for (int j0 = 0; j0 < 64; j0 += 4) {
            float a0[4], a1[4], a2[4], a3[4];
            *(float4*)a0 = *(const float4*)&Ps[(qr + 0) * 68 + j0];
            *(float4*)a1 = *(const float4*)&Ps[(qr + 1) * 68 + j0];
            *(float4*)a2 = *(const float4*)&Ps[(qr + 2) * 68 + j0];
            *(float4*)a3 = *(const float4*)&Ps[(qr + 3) * 68 + j0];
#pragma unroll
            for (int jj = 0; jj < 4; jj++) {
                float b[4];
                *(float4*)b = *(const float4*)&Vs[(j0 + jj) * 64 + dc];
#pragma unroll
                for (int j = 0; j < 4; j++) {
                    o[0][j] = fmaf(a0[jj], b[j], o[0][j]);
                    o[1][j] = fmaf(a1[jj], b[j], o[1][j]);
                    o[2][j] = fmaf(a2[jj], b[j], o[2][j]);
                    o[3][j] = fmaf(a3[jj], b[j], o[3][j]);
                }
            }
        }
    }

    // normalize and write in [B, S, H*dk] (fused head-concat transpose)
    const int b = bh >> 4, h = bh & 15;
    const size_t row0 = (size_t)b * SEQ + (size_t)qt * 64;
#pragma unroll
    for (int i = 0; i < 4; i++) {
        float inv = 1.f / l_i[i];
        float4 ov = make_float4(o[i][0] * inv, o[i][1] * inv,
                                o[i][2] * inv, o[i][3] * inv);
        *(float4*)&Out[(row0 + qr + i) * D_MODEL + h * DK + dc] = ov;
    }
}

// ---------------------------------------------------------------------------
extern "C" void kernel_launch(void* const* d_in, const int* in_sizes, int n_in,
                              void* d_out, int out_size)
{
    const float* query = (const float*)d_in[0];
    const float* key   = (const float*)d_in[1];
    const float* value = (const float*)d_in[2];
    // d_in[3] = mask (int32 tril) — causal handled analytically
    const float* Wq = (const float*)d_in[4];
    const float* bq = (const float*)d_in[5];
    const float* Wk = (const float*)d_in[6];
    const float* bk = (const float*)d_in[7];
    const float* Wv = (const float*)d_in[8];
    const float* bv = (const float*)d_in[9];
    const float* Wo = (const float*)d_in[10];
    const float* bo = (const float*)d_in[11];
    float* out = (float*)d_out;

    float *q, *k, *v, *attn;
    cudaGetSymbolAddress((void**)&q, g_q);
    cudaGetSymbolAddress((void**)&k, g_k);
    cudaGetSymbolAddress((void**)&v, g_v);
    cudaGetSymbolAddress((void**)&attn, g_attn);

    const int flash_smem = (3 * 4096 + 64 * 68) * (int)sizeof(float); // 66560 B
    cudaFuncSetAttribute(flash_kernel,
                         cudaFuncAttributeMaxDynamicSharedMemorySize, flash_smem);

    dim3 gg(D_MODEL / GBN, M_ROWS / GBM);  // (8, 32)
    gemm_bias_kernel<<<gg, 256>>>(query, Wq, bq, q, 1);
    gemm_bias_kernel<<<gg, 256>>>(key,   Wk, bk, k, 1);
    gemm_bias_kernel<<<gg, 256>>>(value, Wv, bv, v, 1);

    dim3 fg(SEQ / 64, BATCH * HEADS);      // (32, 32)
    flash_kernel<<<fg, 256, flash_smem>>>(q, k, v, attn);

    gemm_bias_kernel<<<gg, 256>>>(attn, Wo, bo, out, 0);
}

// round 2
// speedup vs baseline: 1.4300x; 1.4300x over previous
#include <cuda_runtime.h>
#include <cuda_bf16.h>
#include <stdint.h>
#include <math.h>

#define D_MODEL 1024
#define HEADS 16
#define DK 64
#define BATCH 2
#define SEQ 2048
#define M_ROWS (BATCH * SEQ)   // 4096

typedef __nv_bfloat16 bf16;

// ---------------- scratch (static device globals; no allocation) -------------
__device__ float g_q[(size_t)M_ROWS * D_MODEL];
__device__ float g_k[(size_t)M_ROWS * D_MODEL];
__device__ float g_v[(size_t)M_ROWS * D_MODEL];
__device__ float g_attn[(size_t)M_ROWS * D_MODEL];
__device__ bf16  g_ahi[(size_t)M_ROWS * D_MODEL];
__device__ bf16  g_alo[(size_t)M_ROWS * D_MODEL];
__device__ bf16  g_whi[(size_t)D_MODEL * D_MODEL];   // transposed [N][K]
__device__ bf16  g_wlo[(size_t)D_MODEL * D_MODEL];   // transposed [N][K]

// ---------------------------------------------------------------------------
// fp32 -> (hi, lo) bf16 split, in-layout (activations)
// ---------------------------------------------------------------------------
__global__ void __launch_bounds__(256) convert_act_kernel(
    const float* __restrict__ in, bf16* __restrict__ hi, bf16* __restrict__ lo)
{
    int i = blockIdx.x * 256 + threadIdx.x;   // float4 index
    float4 v = ((const float4*)in)[i];
    float f[4] = {v.x, v.y, v.z, v.w};
    union { bf16 h[4]; uint2 u; } uh, ul;
#pragma unroll
    for (int j = 0; j < 4; j++) {
        uh.h[j] = __float2bfloat16(f[j]);
        ul.h[j] = __float2bfloat16(f[j] - __bfloat162float(uh.h[j]));
    }
    ((uint2*)hi)[i] = uh.u;
    ((uint2*)lo)[i] = ul.u;
}

// ---------------------------------------------------------------------------
// fp32 W[K][N] -> bf16 hiT/loT[N][K]  (transposed split, smem tiled)
// ---------------------------------------------------------------------------
__global__ void convert_wT_kernel(const float* __restrict__ W,
                                  bf16* __restrict__ hiT, bf16* __restrict__ loT)
{
    __shared__ float t[32][33];
    const int k0 = blockIdx.x * 32, n0 = blockIdx.y * 32;
    const int tx = threadIdx.x, ty = threadIdx.y;   // 32 x 8
#pragma unroll
    for (int j = 0; j < 4; j++)
        t[ty + j * 8][tx] = W[(size_t)(k0 + ty + j * 8) * D_MODEL + n0 + tx];
    __syncthreads();
#pragma unroll
    for (int j = 0; j < 4; j++) {
        float v = t[tx][ty + j * 8];
        bf16 h = __float2bfloat16(v);
        bf16 l = __float2bfloat16(v - __bfloat162float(h));
        size_t o = (size_t)(n0 + ty + j * 8) * D_MODEL + k0 + tx;
        hiT[o] = h; loT[o] = l;
    }
}

// ---------------------------------------------------------------------------
// GEMM via mma.sync bf16 (3-term split): C[4096,1024] = A*W + bias
// A as (hi,lo)[M][K]; W as (hi,lo)[N][K] transposed. 128x128x32 tiles,
// cp.async double buffer, 8 warps, warp tile 64x32, m16n8k16.
// ---------------------------------------------------------------------------
#define BM 128
#define BN 128
#define BK 32
#define SK 40                              // smem row stride (bf16)
#define MAT_ELEMS (128 * SK)               // 5120 bf16 per matrix tile
#define STAGE_ELEMS (4 * MAT_ELEMS)        // Ahi,Alo,Bhi,Blo

#define LDSM4(R0, R1, R2, R3, ADDR) \
    asm volatile("ldmatrix.sync.aligned.m8n8.x4.shared.b16 {%0,%1,%2,%3}, [%4];" \
        : "=r"(R0), "=r"(R1), "=r"(R2), "=r"(R3) : "r"(ADDR))

#define MMA_BF16(D, A, B) \
    asm volatile("mma.sync.aligned.m16n8k16.row.col.f32.bf16.bf16.f32 " \
        "{%0,%1,%2,%3}, {%4,%5,%6,%7}, {%8,%9}, {%0,%1,%2,%3};" \
        : "+f"(D[0]), "+f"(D[1]), "+f"(D[2]), "+f"(D[3]) \
        : "r"(A[0]), "r"(A[1]), "r"(A[2]), "r"(A[3]), "r"(B[0]), "r"(B[1]))

#define CP16(DST, SRC) \
    asm volatile("cp.async.cg.shared.global [%0], [%1], 16;" :: "r"(DST), "l"(SRC))

__global__ void __launch_bounds__(256) gemm_mma_kernel(
    const bf16* __restrict__ Ahi, const bf16* __restrict__ Alo,
    const bf16* __restrict__ Bhi, const bf16* __restrict__ Blo,
    const float* __restrict__ bias, float* __restrict__ C, int headsplit)
{
    extern __shared__ __align__(16) bf16 sm[];
    const int tid = threadIdx.x;
    const int lane = tid & 31, warp = tid >> 5;
    const int wm = warp >> 2, wn = warp & 3;
    const int m0 = blockIdx.y * BM, n0 = blockIdx.x * BN;

    // cp.async loader mapping: 2 x 16B chunks per thread per matrix
    const int r0 = tid >> 2;                // rows 0..63
    const int cc0 = (tid & 3) * 8;          // bf16 col 0,8,16,24

    uint32_t s_base[2];
    s_base[0] = (uint32_t)__cvta_generic_to_shared(sm);
    s_base[1] = s_base[0] + STAGE_ELEMS * 2;

    const size_t gA0 = (size_t)(m0 + r0) * D_MODEL + cc0;
    const size_t gA1 = (size_t)(m0 + r0 + 64) * D_MODEL + cc0;
    const size_t gB0 = (size_t)(n0 + r0) * D_MODEL + cc0;
    const size_t gB1 = (size_t)(n0 + r0 + 64) * D_MODEL + cc0;
    const uint32_t sOff0 = (uint32_t)(r0 * SK + cc0) * 2;
    const uint32_t sOff1 = (uint32_t)((r0 + 64) * SK + cc0) * 2;

    float acc[4][4][4];
#pragma unroll
    for (int a = 0; a < 4; a++)
#pragma unroll
        for (int b = 0; b < 4; b++)
#pragma unroll
            for (int c = 0; c < 4; c++) acc[a][b][c] = 0.f;

    // ldmatrix lane addressing
    const uint32_t aRow = wm * 64 + (lane & 15);
    const uint32_t aCol = (lane >> 4) * 8;
    const uint32_t bRow = wn * 32 + (lane & 7) + ((lane >> 4) & 1) * 8;
    const uint32_t bCol = ((lane >> 3) & 1) * 8;

#define LOAD_STAGE(S, K0) do { \
    uint32_t sb = s_base[(S) & 1]; \
    CP16(sb + sOff0,                    Ahi + gA0 + (K0)); \
    CP16(sb + sOff1,                    Ahi + gA1 + (K0)); \
    CP16(sb + MAT_ELEMS * 2 + sOff0,    Alo + gA0 + (K0)); \
    CP16(sb + MAT_ELEMS * 2 + sOff1,    Alo + gA1 + (K0)); \
    CP16(sb + 2 * MAT_ELEMS * 2 + sOff0, Bhi + gB0 + (K0)); \
    CP16(sb + 2 * MAT_ELEMS * 2 + sOff1, Bhi + gB1 + (K0)); \
    CP16(sb + 3 * MAT_ELEMS * 2 + sOff0, Blo + gB0 + (K0)); \
    CP16(sb + 3 * MAT_ELEMS * 2 + sOff1, Blo + gB1 + (K0)); \
    asm volatile("cp.async.commit_group;"); \
} while (0)

    LOAD_STAGE(0, 0);

    const int NSTAGE = D_MODEL / BK;   // 32
    for (int s = 0; s < NSTAGE; ++s) {
        asm volatile("cp.async.wait_group 0;" ::: "memory");
        __syncthreads();
        if (s + 1 < NSTAGE) LOAD_STAGE(s + 1, (s + 1) * BK);

        const uint32_t sb = s_base[s & 1];
        const uint32_t aBaseH = sb + (aRow * SK + aCol) * 2;
        const uint32_t aBaseL = aBaseH + MAT_ELEMS * 2;
        const uint32_t bBaseH = sb + 2 * MAT_ELEMS * 2 + (bRow * SK + bCol) * 2;
        const uint32_t bBaseL = bBaseH + MAT_ELEMS * 2;

#pragma unroll
        for (int ks = 0; ks < 2; ++ks) {
            uint32_t ah[4][4], al[4][4], bh[4][2], bl[4][2];
#pragma unroll
            for (int mf = 0; mf < 4; ++mf) {
                uint32_t off = (uint32_t)(mf * 16 * SK + ks * 16) * 2;
                LDSM4(ah[mf][0], ah[mf][1], ah[mf][2], ah[mf][3], aBaseH + off);
                LDSM4(al[mf][0], al[mf][1], al[mf][2], al[mf][3], aBaseL + off);
            }
#pragma unroll
            for (int p = 0; p < 2; ++p) {
                uint32_t off = (uint32_t)(p * 16 * SK + ks * 16) * 2;
                LDSM4(bh[2 * p][0], bh[2 * p][1], bh[2 * p + 1][0], bh[2 * p + 1][1], bBaseH + off);
                LDSM4(bl[2 * p][0], bl[2 * p][1], bl[2 * p + 1][0], bl[2 * p + 1][1], bBaseL + off);
            }
#pragma unroll
            for (int mf = 0; mf < 4; ++mf)
#pragma unroll
                for (int nf = 0; nf < 4; ++nf) {
                    MMA_BF16(acc[mf][nf], ah[mf], bh[nf]);
                    MMA_BF16(acc[mf][nf], ah[mf], bl[nf]);
                    MMA_BF16(acc[mf][nf], al[mf], bh[nf]);
                }
        }
    }

    // epilogue: bias + optional head-split store
    const int l4 = lane >> 2, l2 = (lane & 3) * 2;
#pragma unroll
    for (int mf = 0; mf < 4; ++mf) {
#pragma unroll
        for (int nf = 0; nf < 4; ++nf) {
            const int r = m0 + wm * 64 + mf * 16 + l4;
            const int c = n0 + wn * 32 + nf * 8 + l2;
            const float bx = bias[c], by = bias[c + 1];
            float2 v0 = make_float2(acc[mf][nf][0] + bx, acc[mf][nf][1] + by);
            float2 v1 = make_float2(acc[mf][nf][2] + bx, acc[mf][nf][3] + by);
            if (headsplit) {
                const int b = r >> 11, sx = r & (SEQ - 1);
                const int h = c >> 6, d = c & (DK - 1);
                *(float2*)&C[(((size_t)(b * HEADS + h) * SEQ) + sx) * DK + d] = v0;
                *(float2*)&C[(((size_t)(b * HEADS + h) * SEQ) + sx + 8) * DK + d] = v1;
            } else {
                *(float2*)&C[(size_t)r * D_MODEL + c] = v0;
                *(float2*)&C[(size_t)(r + 8) * D_MODEL + c] = v1;
            }
        }
    }
}

// ---------------------------------------------------------------------------
// Flash attention (causal), fp32 — unchanged from R1.
// ---------------------------------------------------------------------------
__global__ void __launch_bounds__(256) flash_kernel(
    const float* __restrict__ Q, const float* __restrict__ K,
    const float* __restrict__ V, float* __restrict__ Out)
{
    extern __shared__ float smf[];
    float* Qt = smf;             // [64 d][64 q]
    float* Kt = smf + 4096;      // [64 d][64 k]
    float* Vs = smf + 8192;      // [64 k][64 d]
    float* Ps = smf + 12288;     // [64 q][68]

    const int qt = gridDim.x - 1 - blockIdx.x;
    const int bh = blockIdx.y;
    const float* Qp = Q + (size_t)bh * SEQ * DK + (size_t)qt * 64 * DK;
    const float* Kp = K + (size_t)bh * SEQ * DK;
    const float* Vp = V + (size_t)bh * SEQ * DK;

    const int tid = threadIdx.x;
    const int ty = tid >> 4, tx = tid & 15;
    const int qr = ty * 4;
    const int dc = tx * 4;

    float m_i[4], l_i[4], o[4][4];
#pragma unroll
    for (int i = 0; i < 4; i++) {
        m_i[i] = -3.0e38f; l_i[i] = 0.f;
#pragma unroll
        for (int j = 0; j < 4; j++) o[i][j] = 0.f;
    }

#pragma unroll
    for (int it = 0; it < 4; ++it) {
        int idx = tid + it * 256;
        int r = idx >> 4; int c = (idx & 15) << 2;
        float4 qv = *(const float4*)&Qp[r * DK + c];
        Qt[(c + 0) * 64 + r] = qv.x; Qt[(c + 1) * 64 + r] = qv.y;
        Qt[(c + 2) * 64 + r] = qv.z; Qt[(c + 3) * 64 + r] = qv.w;
    }

    const float scale = 0.125f;

    for (int kt = 0; kt <= qt; ++kt) {
        __syncthreads();
#pragma unroll
        for (int it = 0; it < 4; ++it) {
            int idx = tid + it * 256;
            int r = idx >> 4; int c = (idx & 15) << 2;
            float4 kv = *(const float4*)&Kp[(size_t)(kt * 64 + r) * DK + c];
            Kt[(c + 0) * 64 + r] = kv.x; Kt[(c + 1) * 64 + r] = kv.y;
            Kt[(c + 2) * 64 + r] = kv.z; Kt[(c + 3) * 64 + r] = kv.w;
            float4 vv = *(const float4*)&Vp[(size_t)(kt * 64 + r) * DK + c];
            *(float4*)&Vs[r * 64 + c] = vv;
        }
        __syncthreads();

        float s[4][4];
#pragma unroll
        for (int i = 0; i < 4; i++)
#pragma unroll
            for (int j = 0; j < 4; j++) s[i][j] = 0.f;

#pragma unroll 16
        for (int d0 = 0; d0 < 64; ++d0) {
            float a[4], b[4];
            *(float4*)a = *(const float4*)&Qt[d0 * 64 + qr];
            *(float4*)b = *(const float4*)&Kt[d0 * 64 + dc];
#pragma unroll
            for (int i = 0; i < 4; i++)
#pragma unroll
                for (int j = 0; j < 4; j++)
                    s[i][j] = fmaf(a[i], b[j], s[i][j]);
        }

        if (kt == qt) {
#pragma unroll
            for (int i = 0; i < 4; i++)
#pragma unroll
                for (int j = 0; j < 4; j++)
                    s[i][j] = ((dc + j) <= (qr + i)) ? s[i][j] * scale : -1.0e30f;
        } else {
#pragma unroll
            for (int i = 0; i < 4; i++)
#pragma unroll
                for (int j = 0; j < 4; j++) s[i][j] *= scale;
        }

        float mnew[4], corr[4];
#pragma unroll
        for (int i = 0; i < 4; i++) {
            float rm = fmaxf(fmaxf(s[i][0], s[i][1]), fmaxf(s[i][2], s[i][3]));
            rm = fmaxf(rm, __shfl_xor_sync(0xffffffffu, rm, 1));
            rm = fmaxf(rm, __shfl_xor_sync(0xffffffffu, rm, 2));
            rm = fmaxf(rm, __shfl_xor_sync(0xffffffffu, rm, 4));
            rm = fmaxf(rm, __shfl_xor_sync(0xffffffffu, rm, 8));
            mnew[i] = fmaxf(m_i[i], rm);
            corr[i] = __expf(m_i[i] - mnew[i]);
            m_i[i] = mnew[i];
        }
#pragma unroll
        for (int i = 0; i < 4; i++) {
            float sum = 0.f;
#pragma unroll
            for (int j = 0; j < 4; j++) {
                float p = __expf(s[i][j] - mnew[i]);
                s[i][j] = p;
                sum += p;
            }
            sum += __shfl_xor_sync(0xffffffffu, sum, 1);
            sum += __shfl_xor_sync(0xffffffffu, sum, 2);
            sum += __shfl_xor_sync(0xffffffffu, sum, 4);
            sum += __shfl_xor_sync(0xffffffffu, sum, 8);
            l_i[i] = l_i[i] * corr[i] + sum;
#pragma unroll
            for (int j = 0; j < 4; j++) o[i][j] *= corr[i];
            *(float4*)&Ps[(qr + i) * 68 + dc] =
                make_float4(s[i][0], s[i][1], s[i][2], s[i][3]);
        }
        __syncthreads();

#pragma unroll 8
        for (int j0 = 0; j0 < 64; j0 += 4) {
            float a0[4], a1[4], a2[4], a3[4];
            *(float4*)a0 = *(const float4*)&Ps[(qr + 0) * 68 + j0];
            *(float4*)a1 = *(const float4*)&Ps[(qr + 1) * 68 + j0];
            *(float4*)a2 = *(const float4*)&Ps[(qr + 2) * 68 + j0];
            *(float4*)a3 = *(const float4*)&Ps[(qr + 3) * 68 + j0];
#pragma unroll
            for (int jj = 0; jj < 4; jj++) {
                float b[4];
                *(float4*)b = *(const float4*)&Vs[(j0 + jj) * 64 + dc];
#pragma unroll
                for (int j = 0; j < 4; j++) {
                    o[0][j] = fmaf(a0[jj], b[j], o[0][j]);
                    o[1][j] = fmaf(a1[jj], b[j], o[1][j]);
                    o[2][j] = fmaf(a2[jj], b[j], o[2][j]);
                    o[3][j] = fmaf(a3[jj], b[j], o[3][j]);
                }
            }
        }
    }

    const int b = bh >> 4, h = bh & 15;
    const size_t row0 = (size_t)b * SEQ + (size_t)qt * 64;
#pragma unroll
    for (int i = 0; i < 4; i++) {
        float inv = 1.f / l_i[i];
        float4 ov = make_float4(o[i][0] * inv, o[i][1] * inv,
                                o[i][2] * inv, o[i][3] * inv);
        *(float4*)&Out[(row0 + qr + i) * D_MODEL + h * DK + dc] = ov;
    }
}

// ---------------------------------------------------------------------------
extern "C" void kernel_launch(void* const* d_in, const int* in_sizes, int n_in,
                              void* d_out, int out_size)
{
    const float* query = (const float*)d_in[0];
    const float* key   = (const float*)d_in[1];
    const float* value = (const float*)d_in[2];
    // d_in[3] = mask (int32 tril) — causal handled analytically
    const float* Wq = (const float*)d_in[4];
    const float* bq = (const float*)d_in[5];
    const float* Wk = (const float*)d_in[6];
    const float* bk = (const float*)d_in[7];
    const float* Wv = (const float*)d_in[8];
    const float* bv = (const float*)d_in[9];
    const float* Wo = (const float*)d_in[10];
    const float* bo = (const float*)d_in[11];
    float* out = (float*)d_out;

    float *q, *k, *v, *attn;
    bf16 *ahi, *alo, *whi, *wlo;
    cudaGetSymbolAddress((void**)&q, g_q);
    cudaGetSymbolAddress((void**)&k, g_k);
    cudaGetSymbolAddress((void**)&v, g_v);
    cudaGetSymbolAddress((void**)&attn, g_attn);
    cudaGetSymbolAddress((void**)&ahi, g_ahi);
    cudaGetSymbolAddress((void**)&alo, g_alo);
    cudaGetSymbolAddress((void**)&whi, g_whi);
    cudaGetSymbolAddress((void**)&wlo, g_wlo);

    const int flash_smem = (3 * 4096 + 64 * 68) * (int)sizeof(float); // 66560 B
    cudaFuncSetAttribute(flash_kernel,
                         cudaFuncAttributeMaxDynamicSharedMemorySize, flash_smem);
    const int gemm_smem = STAGE_ELEMS * 2 * 2;  // 81920 B
    cudaFuncSetAttribute(gemm_mma_kernel,
                         cudaFuncAttributeMaxDynamicSharedMemorySize, gemm_smem);

    const int nact_blocks = M_ROWS * D_MODEL / 4 / 256;  // 4096
    dim3 wtg(D_MODEL / 32, D_MODEL / 32), wtb(32, 8);
    dim3 gg(D_MODEL / BN, M_ROWS / BM);                  // (8, 32)

    convert_act_kernel<<<nact_blocks, 256>>>(query, ahi, alo);
    convert_wT_kernel<<<wtg, wtb>>>(Wq, whi, wlo);
    gemm_mma_kernel<<<gg, 256, gemm_smem>>>(ahi, alo, whi, wlo, bq, q, 1);

    convert_act_kernel<<<nact_blocks, 256>>>(key, ahi, alo);
    convert_wT_kernel<<<wtg, wtb>>>(Wk, whi, wlo);
    gemm_mma_kernel<<<gg, 256, gemm_smem>>>(ahi, alo, whi, wlo, bk, k, 1);

    convert_act_kernel<<<nact_blocks, 256>>>(value, ahi, alo);
    convert_wT_kernel<<<wtg, wtb>>>(Wv, whi, wlo);
    gemm_mma_kernel<<<gg, 256, gemm_smem>>>(ahi, alo, whi, wlo, bv, v, 1);

    dim3 fg(SEQ / 64, BATCH * HEADS);
    flash_kernel<<<fg, 256, flash_smem>>>(q, k, v, attn);

    convert_act_kernel<<<nact_blocks, 256>>>(attn, ahi, alo);
    convert_wT_kernel<<<wtg, wtb>>>(Wo, whi, wlo);
    gemm_mma_kernel<<<gg, 256, gemm_smem>>>(ahi, alo, whi, wlo, bo, out, 0);
}

// round 3
// speedup vs baseline: 2.6361x; 1.8433x over previous
#include <cuda_runtime.h>
#include <cuda_bf16.h>
#include <stdint.h>
#include <math.h>

#define D_MODEL 1024
#define HEADS 16
#define DK 64
#define BATCH 2
#define SEQ 2048
#define M_ROWS (BATCH * SEQ)   // 4096
#define BH (BATCH * HEADS)     // 32

typedef __nv_bfloat16 bf16;

// ---------------- scratch (static device globals; no allocation) -------------
__device__ bf16 g_ahi[(size_t)M_ROWS * D_MODEL];   // GEMM A hi (also attn out hi)
__device__ bf16 g_alo[(size_t)M_ROWS * D_MODEL];
__device__ bf16 g_whi[(size_t)D_MODEL * D_MODEL];  // W^T hi  [N][K]
__device__ bf16 g_wlo[(size_t)D_MODEL * D_MODEL];
__device__ bf16 g_qhi[(size_t)BH * SEQ * DK];      // [bh][s][d], pre-scaled 0.125
__device__ bf16 g_qlo[(size_t)BH * SEQ * DK];
__device__ bf16 g_khi[(size_t)BH * SEQ * DK];      // [bh][s][d]
__device__ bf16 g_klo[(size_t)BH * SEQ * DK];
__device__ bf16 g_vhi[(size_t)BH * DK * SEQ];      // transposed [bh][d][s]
__device__ bf16 g_vlo[(size_t)BH * DK * SEQ];

// ---------------------------------------------------------------------------
// fp32 -> (hi, lo) bf16 split, in-layout (activations)
// ---------------------------------------------------------------------------
__global__ void __launch_bounds__(256) convert_act_kernel(
    const float* __restrict__ in, bf16* __restrict__ hi, bf16* __restrict__ lo)
{
    int i = blockIdx.x * 256 + threadIdx.x;   // float4 index
    float4 v = ((const float4*)in)[i];
    float f[4] = {v.x, v.y, v.z, v.w};
    union { bf16 h[4]; uint2 u; } uh, ul;
#pragma unroll
    for (int j = 0; j < 4; j++) {
        uh.h[j] = __float2bfloat16(f[j]);
        ul.h[j] = __float2bfloat16(f[j] - __bfloat162float(uh.h[j]));
    }
    ((uint2*)hi)[i] = uh.u;
    ((uint2*)lo)[i] = ul.u;
}

// ---------------------------------------------------------------------------
// fp32 W[K][N] -> bf16 hiT/loT[N][K]  (transposed split, smem tiled)
// ---------------------------------------------------------------------------
__global__ void convert_wT_kernel(const float* __restrict__ W,
                                  bf16* __restrict__ hiT, bf16* __restrict__ loT)
{
    __shared__ float t[32][33];
    const int k0 = blockIdx.x * 32, n0 = blockIdx.y * 32;
    const int tx = threadIdx.x, ty = threadIdx.y;   // 32 x 8
#pragma unroll
    for (int j = 0; j < 4; j++)
        t[ty + j * 8][tx] = W[(size_t)(k0 + ty + j * 8) * D_MODEL + n0 + tx];
    __syncthreads();
#pragma unroll
    for (int j = 0; j < 4; j++) {
        float v = t[tx][ty + j * 8];
        bf16 h = __float2bfloat16(v);
        bf16 l = __float2bfloat16(v - __bfloat162float(h));
        size_t o = (size_t)(n0 + ty + j * 8) * D_MODEL + k0 + tx;
        hiT[o] = h; loT[o] = l;
    }
}

// ---------------------------------------------------------------------------
// MMA building blocks
// ---------------------------------------------------------------------------
#define LDSM4(R0, R1, R2, R3, ADDR) \
    asm volatile("ldmatrix.sync.aligned.m8n8.x4.shared.b16 {%0,%1,%2,%3}, [%4];" \
        : "=r"(R0), "=r"(R1), "=r"(R2), "=r"(R3) : "r"(ADDR))

#define MMA_BF16(D, A, B) \
    asm volatile("mma.sync.aligned.m16n8k16.row.col.f32.bf16.bf16.f32 " \
        "{%0,%1,%2,%3}, {%4,%5,%6,%7}, {%8,%9}, {%0,%1,%2,%3};" \
        : "+f"(D[0]), "+f"(D[1]), "+f"(D[2]), "+f"(D[3]) \
        : "r"(A[0]), "r"(A[1]), "r"(A[2]), "r"(A[3]), "r"(B[0]), "r"(B[1]))

#define CP16(DST, SRC) \
    asm volatile("cp.async.cg.shared.global [%0], [%1], 16;" :: "r"(DST), "l"(SRC))

// ---------------------------------------------------------------------------
// GEMM via mma.sync bf16 (3-term split): C[4096,1024] = A*W + bias
// mode 0: fp32 C row-major.  mode 1: bf16 hi/lo head-split [bh][s][d] (*oscale).
// mode 2: bf16 hi/lo head-split TRANSPOSED [bh][d][s]  (for V).
// ---------------------------------------------------------------------------
#define BM 128
#define BN 128
#define BK 32
#define SK 40
#define MAT_ELEMS (128 * SK)
#define STAGE_ELEMS (4 * MAT_ELEMS)

__global__ void __launch_bounds__(256) gemm_mma_kernel(
    const bf16* __restrict__ Ahi, const bf16* __restrict__ Alo,
    const bf16* __restrict__ Bhi, const bf16* __restrict__ Blo,
    const float* __restrict__ bias, float* __restrict__ Cf,
    bf16* __restrict__ Chi, bf16* __restrict__ Clo, int mode, float oscale)
{
    extern __shared__ __align__(16) bf16 sm[];
    const int tid = threadIdx.x;
    const int lane = tid & 31, warp = tid >> 5;
    const int wm = warp >> 2, wn = warp & 3;
    const int m0 = blockIdx.y * BM, n0 = blockIdx.x * BN;

    const int r0 = tid >> 2;
    const int cc0 = (tid & 3) * 8;

    uint32_t s_base[2];
    s_base[0] = (uint32_t)__cvta_generic_to_shared(sm);
    s_base[1] = s_base[0] + STAGE_ELEMS * 2;

    const size_t gA0 = (size_t)(m0 + r0) * D_MODEL + cc0;
    const size_t gA1 = (size_t)(m0 + r0 + 64) * D_MODEL + cc0;
    const size_t gB0 = (size_t)(n0 + r0) * D_MODEL + cc0;
    const size_t gB1 = (size_t)(n0 + r0 + 64) * D_MODEL + cc0;
    const uint32_t sOff0 = (uint32_t)(r0 * SK + cc0) * 2;
    const uint32_t sOff1 = (uint32_t)((r0 + 64) * SK + cc0) * 2;

    float acc[4][4][4];
#pragma unroll
    for (int a = 0; a < 4; a++)
#pragma unroll
        for (int b = 0; b < 4; b++)
#pragma unroll
            for (int c = 0; c < 4; c++) acc[a][b][c] = 0.f;

    const uint32_t aRow = wm * 64 + (lane & 15);
    const uint32_t aCol = (lane >> 4) * 8;
    const uint32_t bRow = wn * 32 + (lane & 7) + ((lane >> 4) & 1) * 8;
    const uint32_t bCol = ((lane >> 3) & 1) * 8;

#define LOAD_STAGE(S, K0) do { \
    uint32_t sb = s_base[(S) & 1]; \
    CP16(sb + sOff0,                     Ahi + gA0 + (K0)); \
    CP16(sb + sOff1,                     Ahi + gA1 + (K0)); \
    CP16(sb + MAT_ELEMS * 2 + sOff0,     Alo + gA0 + (K0)); \
    CP16(sb + MAT_ELEMS * 2 + sOff1,     Alo + gA1 + (K0)); \
    CP16(sb + 2 * MAT_ELEMS * 2 + sOff0, Bhi + gB0 + (K0)); \
    CP16(sb + 2 * MAT_ELEMS * 2 + sOff1, Bhi + gB1 + (K0)); \
    CP16(sb + 3 * MAT_ELEMS * 2 + sOff0, Blo + gB0 + (K0)); \
    CP16(sb + 3 * MAT_ELEMS * 2 + sOff1, Blo + gB1 + (K0)); \
    asm volatile("cp.async.commit_group;"); \
} while (0)

    LOAD_STAGE(0, 0);

    const int NSTAGE = D_MODEL / BK;
    for (int s = 0; s < NSTAGE; ++s) {
        asm volatile("cp.async.wait_group 0;" ::: "memory");
        __syncthreads();
        if (s + 1 < NSTAGE) LOAD_STAGE(s + 1, (s + 1) * BK);

        const uint32_t sb = s_base[s & 1];
        const uint32_t aBaseH = sb + (aRow * SK + aCol) * 2;
        const uint32_t aBaseL = aBaseH + MAT_ELEMS * 2;
        const uint32_t bBaseH = sb + 2 * MAT_ELEMS * 2 + (bRow * SK + bCol) * 2;
        const uint32_t bBaseL = bBaseH + MAT_ELEMS * 2;

#pragma unroll
        for (int ks = 0; ks < 2; ++ks) {
            uint32_t ah[4][4], al[4][4], bh[4][2], bl[4][2];
#pragma unroll
            for (int mf = 0; mf < 4; ++mf) {
                uint32_t off = (uint32_t)(mf * 16 * SK + ks * 16) * 2;
                LDSM4(ah[mf][0], ah[mf][1], ah[mf][2], ah[mf][3], aBaseH + off);
                LDSM4(al[mf][0], al[mf][1], al[mf][2], al[mf][3], aBaseL + off);
            }
#pragma unroll
            for (int p = 0; p < 2; ++p) {
                uint32_t off = (uint32_t)(p * 16 * SK + ks * 16) * 2;
                LDSM4(bh[2 * p][0], bh[2 * p][1], bh[2 * p + 1][0], bh[2 * p + 1][1], bBaseH + off);
                LDSM4(bl[2 * p][0], bl[2 * p][1], bl[2 * p + 1][0], bl[2 * p + 1][1], bBaseL + off);
            }
#pragma unroll
            for (int mf = 0; mf < 4; ++mf)
#pragma unroll
                for (int nf = 0; nf < 4; ++nf) {
                    MMA_BF16(acc[mf][nf], ah[mf], bh[nf]);
                    MMA_BF16(acc[mf][nf], ah[mf], bl[nf]);
                    MMA_BF16(acc[mf][nf], al[mf], bh[nf]);
                }
        }
    }

    const int l4 = lane >> 2, l2 = (lane & 3) * 2;
#pragma unroll
    for (int mf = 0; mf < 4; ++mf) {
#pragma unroll
        for (int nf = 0; nf < 4; ++nf) {
            const int r = m0 + wm * 64 + mf * 16 + l4;
            const int c = n0 + wn * 32 + nf * 8 + l2;
            const float bx = bias[c], by = bias[c + 1];
            float v00 = acc[mf][nf][0] + bx, v01 = acc[mf][nf][1] + by;
            float v10 = acc[mf][nf][2] + bx, v11 = acc[mf][nf][3] + by;
            if (mode == 0) {
                *(float2*)&Cf[(size_t)r * D_MODEL + c] = make_float2(v00, v01);
                *(float2*)&Cf[(size_t)(r + 8) * D_MODEL + c] = make_float2(v10, v11);
            } else {
                v00 *= oscale; v01 *= oscale; v10 *= oscale; v11 *= oscale;
                const int b = r >> 11, sx = r & (SEQ - 1);
                const int h = c >> 6, d = c & (DK - 1);
                const int bhh = b * HEADS + h;
                if (mode == 1) {
                    __nv_bfloat162 h0 = __floats2bfloat162_rn(v00, v01);
                    __nv_bfloat162 h1 = __floats2bfloat162_rn(v10, v11);
                    __nv_bfloat162 L0 = __floats2bfloat162_rn(v00 - __low2float(h0), v01 - __high2float(h0));
                    __nv_bfloat162 L1 = __floats2bfloat162_rn(v10 - __low2float(h1), v11 - __high2float(h1));
                    size_t o0 = ((size_t)bhh * SEQ + sx) * DK + d;
                    size_t o1 = ((size_t)bhh * SEQ + sx + 8) * DK + d;
                    *(__nv_bfloat162*)&Chi[o0] = h0; *(__nv_bfloat162*)&Clo[o0] = L0;
                    *(__nv_bfloat162*)&Chi[o1] = h1; *(__nv_bfloat162*)&Clo[o1] = L1;
                } else {  // mode 2: transposed [bh][d][s]
                    size_t base = (size_t)bhh * DK * SEQ;
                    float vv[4] = {v00, v01, v10, v11};
                    int dd[4] = {d, d + 1, d, d + 1};
                    int ss[4] = {sx, sx, sx + 8, sx + 8};
#pragma unroll
                    for (int e = 0; e < 4; e++) {
                        bf16 hh = __float2bfloat16(vv[e]);
                        bf16 ll = __float2bfloat16(vv[e] - __bfloat162float(hh));
                        Chi[base + (size_t)dd[e] * SEQ + ss[e]] = hh;
                        Clo[base + (size_t)dd[e] * SEQ + ss[e]] = ll;
                    }
                }
            }
        }
    }
}

// ---------------------------------------------------------------------------
// fast exp on the FMA pipe: e^x = 2^j * e^t,  j=rint(x*log2e), t=(y-j)*ln2
// ---------------------------------------------------------------------------
__device__ __forceinline__ float exp_fast(float x)
{
    float y = fmaxf(x * 1.4426950408889634f, -120.f);
    float jf = y + 12582912.f;                 // 1.5*2^23 magic round
    float jr = jf - 12582912.f;
    float t = (y - jr) * 0.6931471805599453f;  // t in [-0.347, 0.347]
    float p = fmaf(t, 0.008333333f, 0.041666668f);
    p = fmaf(t, p, 0.16666667f);
    p = fmaf(t, p, 0.5f);
    p = fmaf(t, p, 1.0f);
    p = fmaf(t, p, 1.0f);
    int e = (__float_as_int(jf) - 0x4B400000 + 127) << 23;
    return p * __int_as_float(e);
}

// ---------------------------------------------------------------------------
// Flash attention (causal) on tensor cores, bf16 3-term splits, FA2 P-in-reg.
// CTA: 64 q-rows, 4 warps (16 q-rows each). K/V 64-wide tiles, double buffer.
// Q pre-scaled by 0.125 at projection. V is transposed [bh][d][s].
// Writes O directly as bf16 hi/lo into the out-proj A buffers.
// ---------------------------------------------------------------------------
#define FSK 72
#define FTILE (64 * FSK)
#define FSTAGE (4 * FTILE)

__global__ void __launch_bounds__(128) flash_mma_kernel(
    const bf16* __restrict__ Qh, const bf16* __restrict__ Ql,
    const bf16* __restrict__ Kh, const bf16* __restrict__ Kl,
    const bf16* __restrict__ Vh, const bf16* __restrict__ Vl,
    bf16* __restrict__ Ohi, bf16* __restrict__ Olo)
{
    extern __shared__ __align__(16) bf16 fsm[];
    const int tid = threadIdx.x, lane = tid & 31, w = tid >> 5;
    const int qt = gridDim.x - 1 - blockIdx.x, bh = blockIdx.y;

    const uint32_t sb = (uint32_t)__cvta_generic_to_shared(fsm);
    const uint32_t sQh = sb, sQl = sb + FTILE * 2;
    const uint32_t sStage0 = sb + 2 * FTILE * 2;

    const size_t gQ = ((size_t)bh * SEQ + (size_t)qt * 64) * DK;
    const size_t gK = (size_t)bh * SEQ * DK;
    const size_t gV = (size_t)bh * DK * SEQ;

#define FLOADQ() do { \
    _Pragma("unroll") \
    for (int i = 0; i < 4; i++) { \
        int idx = tid + i * 128; int rr = idx >> 3; int cc = (idx & 7) * 8; \
        uint32_t so = (uint32_t)(rr * FSK + cc) * 2; \
        CP16(sQh + so, Qh + gQ + rr * DK + cc); \
        CP16(sQl + so, Ql + gQ + rr * DK + cc); \
    } \
} while (0)

#define FLOADKV(S, KT) do { \
    uint32_t st = sStage0 + (uint32_t)(S) * FSTAGE * 2; \
    _Pragma("unroll") \
    for (int i = 0; i < 4; i++) { \
        int idx = tid + i * 128; int rr = idx >> 3; int cc = (idx & 7) * 8; \
        uint32_t so = (uint32_t)(rr * FSK + cc) * 2; \
        size_t gk = gK + (size_t)((KT) * 64 + rr) * DK + cc; \
        size_t gv = gV + (size_t)rr * SEQ + (KT) * 64 + cc; \
        CP16(st + so,                 Kh + gk); \
        CP16(st + FTILE * 2 + so,     Kl + gk); \
        CP16(st + 2 * FTILE * 2 + so, Vh + gv); \
        CP16(st + 3 * FTILE * 2 + so, Vl + gv); \
    } \
    asm volatile("cp.async.commit_group;"); \
} while (0)

    FLOADQ();
    FLOADKV(0, 0);

    const uint32_t aOff = (uint32_t)((w * 16 + (lane & 15)) * FSK + (lane >> 4) * 8) * 2;
    const uint32_t bRowOff = (lane & 7) + ((lane >> 4) & 1) * 8;
    const uint32_t bColOff = ((lane >> 3) & 1) * 8;

    const int l4 = lane >> 2, l2 = (lane & 3) * 2;
    const int rowBaseA = w * 16 + l4;          // local q row of c0/c1
    float m0 = -3.0e38f, m1 = -3.0e38f, l0 = 0.f, l1 = 0.f;
    float o[8][4];
#pragma unroll
    for (int n = 0; n < 8; n++)
#pragma unroll
        for (int c = 0; c < 4; c++) o[n][c] = 0.f;

    uint32_t qhf[4][4], qlf[4][4];

    for (int kt = 0; kt <= qt; ++kt) {
        asm volatile("cp.async.wait_group 0;" ::: "memory");
        __syncthreads();
        if (kt < qt) FLOADKV((kt + 1) & 1, kt + 1);

        if (kt == 0) {
#pragma unroll
            for (int kk = 0; kk < 4; ++kk) {
                uint32_t off = aOff + (uint32_t)(kk * 16) * 2;
                LDSM4(qhf[kk][0], qhf[kk][1], qhf[kk][2], qhf[kk][3], sQh + off);
                LDSM4(qlf[kk][0], qlf[kk][1], qlf[kk][2], qlf[kk][3], sQl + off);
            }
        }

        const uint32_t stg = sStage0 + (uint32_t)(kt & 1) * FSTAGE * 2;

        // ---- S = Q K^T ----
        float s[8][4];
#pragma unroll
        for (int n = 0; n < 8; n++)
#pragma unroll
            for (int c = 0; c < 4; c++) s[n][c] = 0.f;

#pragma unroll
        for (int kk = 0; kk < 4; ++kk) {
            uint32_t khf[8][2], klf[8][2];
#pragma unroll
            for (int p = 0; p < 4; ++p) {
                uint32_t off = (uint32_t)((p * 16 + bRowOff) * FSK + bColOff + kk * 16) * 2;
                LDSM4(khf[2 * p][0], khf[2 * p][1], khf[2 * p + 1][0], khf[2 * p + 1][1], stg + off);
                LDSM4(klf[2 * p][0], klf[2 * p][1], klf[2 * p + 1][0], klf[2 * p + 1][1], stg + FTILE * 2 + off);
            }
#pragma unroll
            for (int n = 0; n < 8; n++) {
                MMA_BF16(s[n], qhf[kk], khf[n]);
                MMA_BF16(s[n], qhf[kk], klf[n]);
                MMA_BF16(s[n], qlf[kk], khf[n]);
            }
        }

        // ---- online softmax (exp on FMA pipe) ----
        float r0 = -3.0e38f, r1 = -3.0e38f;
#pragma unroll
        for (int n = 0; n < 8; n++) {
            r0 = fmaxf(r0, fmaxf(s[n][0], s[n][1]));
            r1 = fmaxf(r1, fmaxf(s[n][2], s[n][3]));
        }
        r0 = fmaxf(r0, __shfl_xor_sync(0xffffffffu, r0, 1));
        r0 = fmaxf(r0, __shfl_xor_sync(0xffffffffu, r0, 2));
        r1 = fmaxf(r1, __shfl_xor_sync(0xffffffffu, r1, 1));
        r1 = fmaxf(r1, __shfl_xor_sync(0xffffffffu, r1, 2));
        float mn0 = fmaxf(m0, r0), mn1 = fmaxf(m1, r1);
        float corr0 = exp_fast(m0 - mn0), corr1 = exp_fast(m1 - mn1);
        m0 = mn0; m1 = mn1;

        const bool diag = (kt == qt);
        float ls0 = 0.f, ls1 = 0.f;
#pragma unroll
        for (int n = 0; n < 8; n++) {
            float p0 = exp_fast(s[n][0] - mn0);
            float p1 = exp_fast(s[n][1] - mn0);
            float p2 = exp_fast(s[n][2] - mn1);
            float p3 = exp_fast(s[n][3] - mn1);
            if (diag) {
                int cb = n * 8 + l2;
                if (cb > rowBaseA) p0 = 0.f;
                if (cb + 1 > rowBaseA) p1 = 0.f;
                if (cb > rowBaseA + 8) p2 = 0.f;
                if (cb + 1 > rowBaseA + 8) p3 = 0.f;
            }
            s[n][0] = p0; s[n][1] = p1; s[n][2] = p2; s[n][3] = p3;
            ls0 += p0 + p1; ls1 += p2 + p3;
        }
        l0 = l0 * corr0 + ls0;
        l1 = l1 * corr1 + ls1;
#pragma unroll
        for (int n = 0; n < 8; n++) {
            o[n][0] *= corr0; o[n][1] *= corr0;
            o[n][2] *= corr1; o[n][3] *= corr1;
        }

        // ---- pack P to bf16 hi/lo A-fragments (in-register) ----
        uint32_t aPh[4][4], aPl[4][4];
#pragma unroll
        for (int kk = 0; kk < 4; ++kk) {
            const int n0i = 2 * kk, n1i = 2 * kk + 1;
            __nv_bfloat162 h;
            h = __floats2bfloat162_rn(s[n0i][0], s[n0i][1]);
            aPh[kk][0] = *(uint32_t*)&h;
            {   __nv_bfloat162 L = __floats2bfloat162_rn(s[n0i][0] - __low2float(h), s[n0i][1] - __high2float(h));
                aPl[kk][0] = *(uint32_t*)&L; }
            h = __floats2bfloat162_rn(s[n0i][2], s[n0i][3]);
            aPh[kk][1] = *(uint32_t*)&h;
            {   __nv_bfloat162 L = __floats2bfloat162_rn(s[n0i][2] - __low2float(h), s[n0i][3] - __high2float(h));
                aPl[kk][1] = *(uint32_t*)&L; }
            h = __floats2bfloat162_rn(s[n1i][0], s[n1i][1]);
            aPh[kk][2] = *(uint32_t*)&h;
            {   __nv_bfloat162 L = __floats2bfloat162_rn(s[n1i][0] - __low2float(h), s[n1i][1] - __high2float(h));
                aPl[kk][2] = *(uint32_t*)&L; }
            h = __floats2bfloat162_rn(s[n1i][2], s[n1i][3]);
            aPh[kk][3] = *(uint32_t*)&h;
            {   __nv_bfloat162 L = __floats2bfloat162_rn(s[n1i][2] - __low2float(h), s[n1i][3] - __high2float(h));
                aPl[kk][3] = *(uint32_t*)&L; }
        }

        // ---- O += P V ----
#pragma unroll
        for (int kk = 0; kk < 4; ++kk) {
            uint32_t vhf[8][2], vlf[8][2];
#pragma unroll
            for (int p = 0; p < 4; ++p) {
                uint32_t off = (uint32_t)((p * 16 + bRowOff) * FSK + bColOff + kk * 16) * 2;
                LDSM4(vhf[2 * p][0], vhf[2 * p][1], vhf[2 * p + 1][0], vhf[2 * p + 1][1], stg + 2 * FTILE * 2 + off);
                LDSM4(vlf[2 * p][0], vlf[2 * p][1], vlf[2 * p + 1][0], vlf[2 * p + 1][1], stg + 3 * FTILE * 2 + off);
            }
#pragma unroll
            for (int n = 0; n < 8; n++) {
                MMA_BF16(o[n], aPh[kk], vhf[n]);
                MMA_BF16(o[n], aPh[kk], vlf[n]);
                MMA_BF16(o[n], aPl[kk], vhf[n]);
            }
        }
    }

    // ---- epilogue: normalize, split, store as bf16 hi/lo ----
    l0 += __shfl_xor_sync(0xffffffffu, l0, 1);
    l0 += __shfl_xor_sync(0xffffffffu, l0, 2);
    l1 += __shfl_xor_sync(0xffffffffu, l1, 1);
    l1 += __shfl_xor_sync(0xffffffffu, l1, 2);
    const float inv0 = 1.f / l0, inv1 = 1.f / l1;

    const int b = bh >> 4, hh = bh & 15;
    const int grow = qt * 64 + rowBaseA;
    const size_t rbase0 = ((size_t)b * SEQ + grow) * D_MODEL + hh * DK;
    const size_t rbase1 = rbase0 + (size_t)8 * D_MODEL;
#pragma unroll
    for (int n = 0; n < 8; n++) {
        const int d = n * 8 + l2;
        float v0 = o[n][0] * inv0, v1 = o[n][1] * inv0;
        float v2 = o[n][2] * inv1, v3 = o[n][3] * inv1;
        __nv_bfloat162 h0 = __floats2bfloat162_rn(v0, v1);
        __nv_bfloat162 h1 = __floats2bfloat162_rn(v2, v3);
        __nv_bfloat162 L0 = __floats2bfloat162_rn(v0 - __low2float(h0), v1 - __high2float(h0));
        __nv_bfloat162 L1 = __floats2bfloat162_rn(v2 - __low2float(h1), v3 - __high2float(h1));
        *(__nv_bfloat162*)&Ohi[rbase0 + d] = h0;
        *(__nv_bfloat162*)&Olo[rbase0 + d] = L0;
        *(__nv_bfloat162*)&Ohi[rbase1 + d] = h1;
        *(__nv_bfloat162*)&Olo[rbase1 + d] = L1;
    }
}

// ---------------------------------------------------------------------------
extern "C" void kernel_launch(void* const* d_in, const int* in_sizes, int n_in,
                              void* d_out, int out_size)
{
    const float* query = (const float*)d_in[0];
    const float* key   = (const float*)d_in[1];
    const float* value = (const float*)d_in[2];
    // d_in[3] = mask (causal handled analytically)
    const float* Wq = (const float*)d_in[4];
    const float* bq = (const float*)d_in[5];
    const float* Wk = (const float*)d_in[6];
    const float* bk = (const float*)d_in[7];
    const float* Wv = (const float*)d_in[8];
    const float* bv = (const float*)d_in[9];
    const float* Wo = (const float*)d_in[10];
    const float* bo = (const float*)d_in[11];
    float* out = (float*)d_out;

    bf16 *ahi, *alo, *whi, *wlo, *qhi, *qlo, *khi, *klo, *vhi, *vlo;
    cudaGetSymbolAddress((void**)&ahi, g_ahi);
    cudaGetSymbolAddress((void**)&alo, g_alo);
    cudaGetSymbolAddress((void**)&whi, g_whi);
    cudaGetSymbolAddress((void**)&wlo, g_wlo);
    cudaGetSymbolAddress((void**)&qhi, g_qhi);
    cudaGetSymbolAddress((void**)&qlo, g_qlo);
    cudaGetSymbolAddress((void**)&khi, g_khi);
    cudaGetSymbolAddress((void**)&klo, g_klo);
    cudaGetSymbolAddress((void**)&vhi, g_vhi);
    cudaGetSymbolAddress((void**)&vlo, g_vlo);

    const int gemm_smem = STAGE_ELEMS * 2 * 2;                  // 81920 B
    cudaFuncSetAttribute(gemm_mma_kernel,
                         cudaFuncAttributeMaxDynamicSharedMemorySize, gemm_smem);
    const int flash_smem = (2 * FTILE + 2 * FSTAGE) * 2;        // 92160 B
    cudaFuncSetAttribute(flash_mma_kernel,
                         cudaFuncAttributeMaxDynamicSharedMemorySize, flash_smem);

    const int nact_blocks = M_ROWS * D_MODEL / 4 / 256;
    dim3 wtg(D_MODEL / 32, D_MODEL / 32), wtb(32, 8);
    dim3 gg(D_MODEL / BN, M_ROWS / BM);

    convert_act_kernel<<<nact_blocks, 256>>>(query, ahi, alo);
    convert_wT_kernel<<<wtg, wtb>>>(Wq, whi, wlo);
    gemm_mma_kernel<<<gg, 256, gemm_smem>>>(ahi, alo, whi, wlo, bq,
                                            nullptr, qhi, qlo, 1, 0.125f);

    convert_act_kernel<<<nact_blocks, 256>>>(key, ahi, alo);
    convert_wT_kernel<<<wtg, wtb>>>(Wk, whi, wlo);
    gemm_mma_kernel<<<gg, 256, gemm_smem>>>(ahi, alo, whi, wlo, bk,
                                            nullptr, khi, klo, 1, 1.0f);

    convert_act_kernel<<<nact_blocks, 256>>>(value, ahi, alo);
    convert_wT_kernel<<<wtg, wtb>>>(Wv, whi, wlo);
    gemm_mma_kernel<<<gg, 256, gemm_smem>>>(ahi, alo, whi, wlo, bv,
                                            nullptr, vhi, vlo, 2, 1.0f);

    dim3 fg(SEQ / 64, BH);
    flash_mma_kernel<<<fg, 128, flash_smem>>>(qhi, qlo, khi, klo, vhi, vlo,
                                              ahi, alo);

    convert_wT_kernel<<<wtg, wtb>>>(Wo, whi, wlo);
    gemm_mma_kernel<<<gg, 256, gemm_smem>>>(ahi, alo, whi, wlo, bo,
                                            out, nullptr, nullptr, 0, 1.0f);
}